// round 9
// baseline (speedup 1.0000x reference)
#include <cuda_runtime.h>

// out = outer(w, x) @ x0 + bias + x  ==  w * dot(x, x0) + bias + x
// D = 8192 floats = 2048 float4.
// 8 CTAs x 256 threads, single launch, one barrier (R6 structure, best=6.56us).
// R9: truncate warp shfl-tree at 3 steps (saves 2x26 cyc of serial SHFL);
// each warp leaves 4 partials in smem (32 total), every thread broadcast-loads
// all 32 via 8x LDS.128 and folds locally.

#define NCTAS 8
#define NTHR  256
#define NWARP (NTHR / 32)
#define V4_TOTAL 2048
#define V4_PER_T (V4_TOTAL / NTHR)    // 8
#define V4_PER_CTA (V4_TOTAL / NCTAS) // 256

__global__ void __launch_bounds__(NTHR) cross_fused_kernel(const float4* __restrict__ x0,
                                                           const float4* __restrict__ x,
                                                           const float4* __restrict__ w,
                                                           const float4* __restrict__ b,
                                                           float4* __restrict__ out) {
    const int t = threadIdx.x;

    // ---- Front-batch ALL loads (19 independent LDG.128) ----
    float4 a[V4_PER_T], xv[V4_PER_T];
    #pragma unroll
    for (int k = 0; k < V4_PER_T; k++) {
        a[k]  = x0[t + k * NTHR];
        xv[k] = x[t + k * NTHR];
    }
    const int ei = blockIdx.x * V4_PER_CTA + t;
    float4 wv = w[ei];
    float4 bv = b[ei];
    float4 xe = x[ei];

    // Epilogue additive part — independent of the reduction, fold early.
    float4 cv;
    cv.x = bv.x + xe.x;
    cv.y = bv.y + xe.y;
    cv.z = bv.z + xe.z;
    cv.w = bv.w + xe.w;

    // ---- Partial dot (tree-reassociated, 4 independent chains) ----
    float p[V4_PER_T];
    #pragma unroll
    for (int k = 0; k < V4_PER_T; k++) {
        p[k] = (a[k].x * xv[k].x + a[k].y * xv[k].y)
             + (a[k].z * xv[k].z + a[k].w * xv[k].w);
    }
    float s = ((p[0] + p[1]) + (p[2] + p[3]))
            + ((p[4] + p[5]) + (p[6] + p[7]));

    // ---- Truncated warp reduction: 3 shfl steps only ----
    // After xor 16,8,4: each lane holds the sum over the 8 lanes sharing
    // (lane & 3). Lanes 0..3 hold 4 distinct partials; their sum = warp sum.
    s += __shfl_xor_sync(0xFFFFFFFFu, s, 16);
    s += __shfl_xor_sync(0xFFFFFFFFu, s, 8);
    s += __shfl_xor_sync(0xFFFFFFFFu, s, 4);

    __shared__ float4 ws4[NWARP];   // 8 warps x 4 partials = 32 floats
    float* ws = (float*)ws4;
    const int warp = t >> 5;
    const int lane = t & 31;
    if (lane < 4) ws[warp * 4 + lane] = s;
    __syncthreads();

    // Broadcast-load all 32 partials (8x LDS.128), fold in a 5-deep add tree.
    float4 u0 = ws4[0], u1 = ws4[1], u2 = ws4[2], u3 = ws4[3];
    float4 u4 = ws4[4], u5 = ws4[5], u6 = ws4[6], u7 = ws4[7];
    float4 q0, q1;
    q0.x = u0.x + u1.x; q0.y = u0.y + u1.y; q0.z = u0.z + u1.z; q0.w = u0.w + u1.w;
    q1.x = u2.x + u3.x; q1.y = u2.y + u3.y; q1.z = u2.z + u3.z; q1.w = u2.w + u3.w;
    float4 q2, q3;
    q2.x = u4.x + u5.x; q2.y = u4.y + u5.y; q2.z = u4.z + u5.z; q2.w = u4.w + u5.w;
    q3.x = u6.x + u7.x; q3.y = u6.y + u7.y; q3.z = u6.z + u7.z; q3.w = u6.w + u7.w;
    float4 r0, r1;
    r0.x = q0.x + q1.x; r0.y = q0.y + q1.y; r0.z = q0.z + q1.z; r0.w = q0.w + q1.w;
    r1.x = q2.x + q3.x; r1.y = q2.y + q3.y; r1.z = q2.z + q3.z; r1.w = q2.w + q3.w;
    const float sv = ((r0.x + r1.x) + (r0.y + r1.y))
                   + ((r0.z + r1.z) + (r0.w + r1.w));

    // ---- Epilogue: out = w*s + (b + x) ----
    float4 o;
    o.x = fmaf(wv.x, sv, cv.x);
    o.y = fmaf(wv.y, sv, cv.y);
    o.z = fmaf(wv.z, sv, cv.z);
    o.w = fmaf(wv.w, sv, cv.w);
    out[ei] = o;
}

extern "C" void kernel_launch(void* const* d_in, const int* in_sizes, int n_in,
                              void* d_out, int out_size) {
    const float4* x0 = (const float4*)d_in[0];
    const float4* x  = (const float4*)d_in[1];
    const float4* w  = (const float4*)d_in[2];
    const float4* b  = (const float4*)d_in[3];
    float4* out = (float4*)d_out;

    cross_fused_kernel<<<NCTAS, NTHR>>>(x0, x, w, b, out);
}